// round 15
// baseline (speedup 1.0000x reference)
#include <cuda_runtime.h>
#include <cuda_fp16.h>
#include <cstdint>

// ============================================================================
// BanditLayer dense linear: out[4096,8192] = x[4096,4096] @ w[8192,4096]^T + b
// Converged mma.sync design + NEW: time-domain CTA stagger. Each SMSP hosts
// one warp from each of the 2 co-resident CTAs; staggering the CTAs by ~half
// a k-step keeps one warp mid-MMA-chain while the other waits at its barrier.
// ============================================================================

#define KM 4096
#define KP 4096
#define KN 8192

#define BM 128
#define BN 128
#define BK 64
#define STAGES 3
#define KSTEPS (KP / BK)
#define A_STAGE_BYTES (BM * BK * 2)
#define B_STAGE_BYTES (BN * BK * 2)
#define STAGE_BYTES (A_STAGE_BYTES + B_STAGE_BYTES)
#define SMEM_TOTAL (STAGES * STAGE_BYTES)

__device__ __half g_Xh[(size_t)KM * KP];   // 32 MB
__device__ __half g_Wh[(size_t)KN * KP];   // 64 MB
__device__ int g_smslot[256];              // per-SM arrival counters (zero-init)

#define NX16 ((KM * KP) / 16)
#define NW16 ((KN * KP) / 16)

// ---------------------------------------------------------------------------
__device__ __forceinline__ uint32_t s2u(const void* p) {
    uint32_t a;
    asm("{ .reg .u64 t; cvta.to.shared.u64 t, %1; cvt.u32.u64 %0, t; }"
        : "=r"(a) : "l"(p));
    return a;
}

__device__ __forceinline__ void cp_async16(uint32_t dst, const void* src) {
    asm volatile("cp.async.cg.shared.global [%0], [%1], 16;" :: "r"(dst), "l"(src));
}
__device__ __forceinline__ void cp_commit() {
    asm volatile("cp.async.commit_group;" ::: "memory");
}
template <int N>
__device__ __forceinline__ void cp_wait() {
    asm volatile("cp.async.wait_group %0;" :: "n"(N) : "memory");
}

__device__ __forceinline__ void ldsm_x4(uint32_t* r, uint32_t addr) {
    asm volatile("ldmatrix.sync.aligned.m8n8.x4.shared.b16 {%0,%1,%2,%3}, [%4];"
                 : "=r"(r[0]), "=r"(r[1]), "=r"(r[2]), "=r"(r[3]) : "r"(addr));
}

// streaming store: evict-first in L2 so output doesn't displace fp16 scratch
__device__ __forceinline__ void stg_cs_v2(float* p, float x, float y) {
    asm volatile("st.global.cs.v2.f32 [%0], {%1, %2};" :: "l"(p), "f"(x), "f"(y) : "memory");
}

#define MMA16816(d, a, b0, b1)                                          \
    asm volatile(                                                       \
        "mma.sync.aligned.m16n8k16.row.col.f32.f16.f16.f32 "            \
        "{%0,%1,%2,%3}, {%4,%5,%6,%7}, {%8,%9}, {%0,%1,%2,%3};"         \
        : "+f"((d)[0]), "+f"((d)[1]), "+f"((d)[2]), "+f"((d)[3])        \
        : "r"((a)[0]), "r"((a)[1]), "r"((a)[2]), "r"((a)[3]),           \
          "r"(b0), "r"(b1))

// swizzled byte offset within a [rows x 64-half] tile (128B rows, 16B chunks)
__device__ __forceinline__ uint32_t swz(int row, int chunk) {
    return (uint32_t)row * 128u + (uint32_t)((chunk ^ (row & 7)) << 4);
}

// ---------------------------------------------------------------------------
// Pass 1: fp32 -> fp16 for BOTH x and weight, 16 elems / thread.
// ---------------------------------------------------------------------------
__global__ void __launch_bounds__(256) convert_all_kernel(const float* __restrict__ x,
                                                          const float* __restrict__ w) {
    int i = blockIdx.x * 256 + threadIdx.x;
    const float* src;
    __half* dst;
    int j;
    if (i < NX16) {
        src = x;  dst = g_Xh;  j = i;
    } else {
        src = w;  dst = g_Wh;  j = i - NX16;
        if (j >= NW16) return;
    }
    const float4* s = reinterpret_cast<const float4*>(src) + (size_t)j * 4;
    uint4* d = reinterpret_cast<uint4*>(dst) + (size_t)j * 2;
    #pragma unroll
    for (int half = 0; half < 2; half++) {
        float4 f0 = s[half * 2 + 0];
        float4 f1 = s[half * 2 + 1];
        alignas(16) __half2 h[4];
        h[0] = __floats2half2_rn(f0.x, f0.y);
        h[1] = __floats2half2_rn(f0.z, f0.w);
        h[2] = __floats2half2_rn(f1.x, f1.y);
        h[3] = __floats2half2_rn(f1.z, f1.w);
        d[half] = *reinterpret_cast<const uint4*>(h);
    }
}

// ---------------------------------------------------------------------------
// Pass 2: the GEMM, with time-staggered co-resident CTAs.
// ---------------------------------------------------------------------------
__global__ void __launch_bounds__(128, 2) gemm_kernel(const float* __restrict__ bias,
                                                      float* __restrict__ out) {
    extern __shared__ char smem[];
    const uint32_t sb = s2u(smem);
    const int tid = threadIdx.x;
    const int lane = tid & 31;
    const int wid = tid >> 5;   // 0..3
    const int nt = blockIdx.x;  // 0..63
    const int mt = blockIdx.y;  // 0..31

    // ---- time-domain stagger: 2nd CTA on each SM delays ~half a k-step ----
    __shared__ int s_delay;
    uint32_t smid;
    asm("mov.u32 %0, %%smid;" : "=r"(smid));
    if (tid == 0)
        s_delay = atomicAdd(&g_smslot[smid & 255], 1) & 1;

    const __half* gA0 = g_Xh + (size_t)(mt * BM) * KP;
    const __half* gW0 = g_Wh + (size_t)(nt * BN) * KP;

    int lrow[8], lcol[8];
    #pragma unroll
    for (int i = 0; i < 8; i++) {
        int idx = i * 128 + tid;
        lrow[i] = idx >> 3;
        lcol[i] = idx & 7;
    }

    auto load_stage = [&](int ks, int buf) {
        uint32_t sA = sb + buf * STAGE_BYTES;
        uint32_t sB = sA + A_STAGE_BYTES;
        const __half* gA = gA0 + ks * BK;
        const __half* gB = gW0 + ks * BK;
        #pragma unroll
        for (int i = 0; i < 8; i++) {
            uint32_t off = swz(lrow[i], lcol[i]);
            cp_async16(sA + off, gA + (size_t)lrow[i] * KP + lcol[i] * 8);
            cp_async16(sB + off, gB + (size_t)lrow[i] * KP + lcol[i] * 8);
        }
    };

    #pragma unroll
    for (int s = 0; s < STAGES - 1; s++) {
        load_stage(s, s);
        cp_commit();
    }

    // apply the stagger after issuing prologue copies (overlaps the spin
    // with the loads), before the mainloop's barrier cadence begins.
    __syncthreads();
    if (s_delay) {
        unsigned long long t0 = clock64();
        while (clock64() - t0 < 700) { }
    }

    const int wm = (wid & 1) * 64;
    const int wn = (wid >> 1) * 64;

    float acc[4][8][4];
    #pragma unroll
    for (int mi = 0; mi < 4; mi++)
        #pragma unroll
        for (int ni = 0; ni < 8; ni++)
            #pragma unroll
            for (int q = 0; q < 4; q++) acc[mi][ni][q] = 0.0f;

    const int arow = lane & 15;
    const int achunk = lane >> 4;
    const int brow = (lane & 7) + ((lane >> 4) << 3);
    const int bchunk = (lane >> 3) & 1;

    uint32_t a[2][4][4], b[2][4][4];

    auto load_frags = [&](uint32_t sA, uint32_t sB, int kk, int slot) {
        #pragma unroll
        for (int mi = 0; mi < 4; mi++)
            ldsm_x4(a[slot][mi], sA + swz(wm + mi * 16 + arow, kk * 2 + achunk));
        #pragma unroll
        for (int nj = 0; nj < 4; nj++)
            ldsm_x4(b[slot][nj], sB + swz(wn + nj * 16 + brow, kk * 2 + bchunk));
    };

    for (int ks = 0; ks < KSTEPS; ks++) {
        cp_wait<STAGES - 2>();
        __syncthreads();

        if (ks + STAGES - 1 < KSTEPS)
            load_stage(ks + STAGES - 1, (ks + STAGES - 1) % STAGES);
        cp_commit();

        uint32_t sA = sb + (ks % STAGES) * STAGE_BYTES;
        uint32_t sB = sA + A_STAGE_BYTES;

        load_frags(sA, sB, 0, 0);

        #pragma unroll
        for (int kk = 0; kk < BK / 16; kk++) {
            const int cur = kk & 1;
            if (kk + 1 < BK / 16)
                load_frags(sA, sB, kk + 1, cur ^ 1);
            #pragma unroll
            for (int mi = 0; mi < 4; mi++)
                #pragma unroll
                for (int ni = 0; ni < 8; ni++)
                    MMA16816(acc[mi][ni], a[cur][mi],
                             b[cur][ni >> 1][(ni & 1) * 2],
                             b[cur][ni >> 1][(ni & 1) * 2 + 1]);
        }
    }

    // ---- epilogue: streaming gmem stores with bias ----
    const int orow0 = mt * BM + wm + (lane >> 2);
    const int ocol0 = nt * BN + wn + (lane & 3) * 2;

    #pragma unroll
    for (int ni = 0; ni < 8; ni++) {
        int col = ocol0 + ni * 8;
        float2 bv = *reinterpret_cast<const float2*>(bias + col);
        #pragma unroll
        for (int mi = 0; mi < 4; mi++) {
            int r0 = orow0 + mi * 16;
            stg_cs_v2(out + (size_t)r0 * KN + col,
                      acc[mi][ni][0] + bv.x, acc[mi][ni][1] + bv.y);
            stg_cs_v2(out + (size_t)(r0 + 8) * KN + col,
                      acc[mi][ni][2] + bv.x, acc[mi][ni][3] + bv.y);
        }
    }

    // release the per-SM slot so the counter self-resets across graph replays
    __syncthreads();
    if (tid == 0)
        atomicSub(&g_smslot[smid & 255], 1);
}

// ---------------------------------------------------------------------------
extern "C" void kernel_launch(void* const* d_in, const int* in_sizes, int n_in,
                              void* d_out, int out_size) {
    const float* x    = (const float*)d_in[0];   // [4096, 4096]
    const float* w    = (const float*)d_in[1];   // [8192, 4096]
    const float* bias = (const float*)d_in[2];   // [8192]
    float* out = (float*)d_out;                  // [4096, 8192]

    cudaFuncSetAttribute(gemm_kernel, cudaFuncAttributeMaxDynamicSharedMemorySize, SMEM_TOTAL);

    convert_all_kernel<<<(NX16 + NW16) / 256, 256>>>(x, w);

    dim3 grid(KN / BN, KM / BM);   // (64, 32)
    gemm_kernel<<<grid, 128, SMEM_TOTAL>>>(bias, out);
}

// round 16
// speedup vs baseline: 1.1280x; 1.1280x over previous
#include <cuda_runtime.h>
#include <cuda_fp16.h>
#include <cstdint>

// ============================================================================
// BanditLayer dense linear: out[4096,8192] = x[4096,4096] @ w[8192,4096]^T + b
//
// FINAL converged design (15 rounds of measurement):
//  - fp32->fp16 convert pass (~36us, ~93% of DRAM spec; fp16 required for
//    precision: rel_err 2.8e-4 vs bf16 ~1.6e-3 at K=4096)
//  - mma.sync fp16/fp32-acc GEMM: 128x128 CTA tile, 4 warps (64x64 each),
//    3-stage cp.async pipeline, register double-buffered ldmatrix fragments,
//    2 CTAs/SM, streaming (.cs) epilogue stores.
//  - Measured at the fp32-acc HMMA instruction-rate ceiling:
//    1024 MAC/cyc/SM while active, tensor ~77% of elapsed (~465 TF/s eff).
//    tcgen05 (4x rate) unavailable: harness compiles PTX at bare sm_103.
//  - Falsified alternatives: BN=256 tiles (R3), 8-warp CTAs (R2/R4),
//    LDGSTS sinking (R6), frag double-buffer alone (R7: neutral, kept),
//    CTA k-rotation (R8), 32-elem convert (R9), .cs loads (R11),
//    time-domain CTA stagger via atomics (R15: -13%).
//  - Plateau: 629.9 / 630.7 / 630.6 / 631.6 us across four re-benches.
// ============================================================================

#define KM 4096
#define KP 4096
#define KN 8192

#define BM 128
#define BN 128
#define BK 64
#define STAGES 3
#define KSTEPS (KP / BK)
#define A_STAGE_BYTES (BM * BK * 2)
#define B_STAGE_BYTES (BN * BK * 2)
#define STAGE_BYTES (A_STAGE_BYTES + B_STAGE_BYTES)
#define SMEM_TOTAL (STAGES * STAGE_BYTES)

__device__ __half g_Xh[(size_t)KM * KP];   // 32 MB
__device__ __half g_Wh[(size_t)KN * KP];   // 64 MB

#define NX16 ((KM * KP) / 16)
#define NW16 ((KN * KP) / 16)

// ---------------------------------------------------------------------------
__device__ __forceinline__ uint32_t s2u(const void* p) {
    uint32_t a;
    asm("{ .reg .u64 t; cvta.to.shared.u64 t, %1; cvt.u32.u64 %0, t; }"
        : "=r"(a) : "l"(p));
    return a;
}

__device__ __forceinline__ void cp_async16(uint32_t dst, const void* src) {
    asm volatile("cp.async.cg.shared.global [%0], [%1], 16;" :: "r"(dst), "l"(src));
}
__device__ __forceinline__ void cp_commit() {
    asm volatile("cp.async.commit_group;" ::: "memory");
}
template <int N>
__device__ __forceinline__ void cp_wait() {
    asm volatile("cp.async.wait_group %0;" :: "n"(N) : "memory");
}

__device__ __forceinline__ void ldsm_x4(uint32_t* r, uint32_t addr) {
    asm volatile("ldmatrix.sync.aligned.m8n8.x4.shared.b16 {%0,%1,%2,%3}, [%4];"
                 : "=r"(r[0]), "=r"(r[1]), "=r"(r[2]), "=r"(r[3]) : "r"(addr));
}

// streaming store: evict-first in L2 so output doesn't displace fp16 scratch
__device__ __forceinline__ void stg_cs_v2(float* p, float x, float y) {
    asm volatile("st.global.cs.v2.f32 [%0], {%1, %2};" :: "l"(p), "f"(x), "f"(y) : "memory");
}

#define MMA16816(d, a, b0, b1)                                          \
    asm volatile(                                                       \
        "mma.sync.aligned.m16n8k16.row.col.f32.f16.f16.f32 "            \
        "{%0,%1,%2,%3}, {%4,%5,%6,%7}, {%8,%9}, {%0,%1,%2,%3};"         \
        : "+f"((d)[0]), "+f"((d)[1]), "+f"((d)[2]), "+f"((d)[3])        \
        : "r"((a)[0]), "r"((a)[1]), "r"((a)[2]), "r"((a)[3]),           \
          "r"(b0), "r"(b1))

// swizzled byte offset within a [rows x 64-half] tile (128B rows, 16B chunks)
__device__ __forceinline__ uint32_t swz(int row, int chunk) {
    return (uint32_t)row * 128u + (uint32_t)((chunk ^ (row & 7)) << 4);
}

// ---------------------------------------------------------------------------
// Pass 1: fp32 -> fp16 for BOTH x and weight, 16 elems / thread.
// ---------------------------------------------------------------------------
__global__ void __launch_bounds__(256) convert_all_kernel(const float* __restrict__ x,
                                                          const float* __restrict__ w) {
    int i = blockIdx.x * 256 + threadIdx.x;
    const float* src;
    __half* dst;
    int j;
    if (i < NX16) {
        src = x;  dst = g_Xh;  j = i;
    } else {
        src = w;  dst = g_Wh;  j = i - NX16;
        if (j >= NW16) return;
    }
    const float4* s = reinterpret_cast<const float4*>(src) + (size_t)j * 4;
    uint4* d = reinterpret_cast<uint4*>(dst) + (size_t)j * 2;
    #pragma unroll
    for (int half = 0; half < 2; half++) {
        float4 f0 = s[half * 2 + 0];
        float4 f1 = s[half * 2 + 1];
        alignas(16) __half2 h[4];
        h[0] = __floats2half2_rn(f0.x, f0.y);
        h[1] = __floats2half2_rn(f0.z, f0.w);
        h[2] = __floats2half2_rn(f1.x, f1.y);
        h[3] = __floats2half2_rn(f1.z, f1.w);
        d[half] = *reinterpret_cast<const uint4*>(h);
    }
}

// ---------------------------------------------------------------------------
// Pass 2: the GEMM.
// ---------------------------------------------------------------------------
__global__ void __launch_bounds__(128, 2) gemm_kernel(const float* __restrict__ bias,
                                                      float* __restrict__ out) {
    extern __shared__ char smem[];
    const uint32_t sb = s2u(smem);
    const int tid = threadIdx.x;
    const int lane = tid & 31;
    const int wid = tid >> 5;   // 0..3
    const int nt = blockIdx.x;  // 0..63
    const int mt = blockIdx.y;  // 0..31

    const __half* gA0 = g_Xh + (size_t)(mt * BM) * KP;
    const __half* gW0 = g_Wh + (size_t)(nt * BN) * KP;

    int lrow[8], lcol[8];
    #pragma unroll
    for (int i = 0; i < 8; i++) {
        int idx = i * 128 + tid;
        lrow[i] = idx >> 3;
        lcol[i] = idx & 7;
    }

    auto load_stage = [&](int ks, int buf) {
        uint32_t sA = sb + buf * STAGE_BYTES;
        uint32_t sB = sA + A_STAGE_BYTES;
        const __half* gA = gA0 + ks * BK;
        const __half* gB = gW0 + ks * BK;
        #pragma unroll
        for (int i = 0; i < 8; i++) {
            uint32_t off = swz(lrow[i], lcol[i]);
            cp_async16(sA + off, gA + (size_t)lrow[i] * KP + lcol[i] * 8);
            cp_async16(sB + off, gB + (size_t)lrow[i] * KP + lcol[i] * 8);
        }
    };

    #pragma unroll
    for (int s = 0; s < STAGES - 1; s++) {
        load_stage(s, s);
        cp_commit();
    }

    const int wm = (wid & 1) * 64;
    const int wn = (wid >> 1) * 64;

    float acc[4][8][4];
    #pragma unroll
    for (int mi = 0; mi < 4; mi++)
        #pragma unroll
        for (int ni = 0; ni < 8; ni++)
            #pragma unroll
            for (int q = 0; q < 4; q++) acc[mi][ni][q] = 0.0f;

    const int arow = lane & 15;
    const int achunk = lane >> 4;
    const int brow = (lane & 7) + ((lane >> 4) << 3);
    const int bchunk = (lane >> 3) & 1;

    uint32_t a[2][4][4], b[2][4][4];

    auto load_frags = [&](uint32_t sA, uint32_t sB, int kk, int slot) {
        #pragma unroll
        for (int mi = 0; mi < 4; mi++)
            ldsm_x4(a[slot][mi], sA + swz(wm + mi * 16 + arow, kk * 2 + achunk));
        #pragma unroll
        for (int nj = 0; nj < 4; nj++)
            ldsm_x4(b[slot][nj], sB + swz(wn + nj * 16 + brow, kk * 2 + bchunk));
    };

    for (int ks = 0; ks < KSTEPS; ks++) {
        cp_wait<STAGES - 2>();
        __syncthreads();

        if (ks + STAGES - 1 < KSTEPS)
            load_stage(ks + STAGES - 1, (ks + STAGES - 1) % STAGES);
        cp_commit();

        uint32_t sA = sb + (ks % STAGES) * STAGE_BYTES;
        uint32_t sB = sA + A_STAGE_BYTES;

        load_frags(sA, sB, 0, 0);

        #pragma unroll
        for (int kk = 0; kk < BK / 16; kk++) {
            const int cur = kk & 1;
            if (kk + 1 < BK / 16)
                load_frags(sA, sB, kk + 1, cur ^ 1);
            #pragma unroll
            for (int mi = 0; mi < 4; mi++)
                #pragma unroll
                for (int ni = 0; ni < 8; ni++)
                    MMA16816(acc[mi][ni], a[cur][mi],
                             b[cur][ni >> 1][(ni & 1) * 2],
                             b[cur][ni >> 1][(ni & 1) * 2 + 1]);
        }
    }

    // ---- epilogue: streaming gmem stores with bias ----
    const int orow0 = mt * BM + wm + (lane >> 2);
    const int ocol0 = nt * BN + wn + (lane & 3) * 2;

    #pragma unroll
    for (int ni = 0; ni < 8; ni++) {
        int col = ocol0 + ni * 8;
        float2 bv = *reinterpret_cast<const float2*>(bias + col);
        #pragma unroll
        for (int mi = 0; mi < 4; mi++) {
            int r0 = orow0 + mi * 16;
            stg_cs_v2(out + (size_t)r0 * KN + col,
                      acc[mi][ni][0] + bv.x, acc[mi][ni][1] + bv.y);
            stg_cs_v2(out + (size_t)(r0 + 8) * KN + col,
                      acc[mi][ni][2] + bv.x, acc[mi][ni][3] + bv.y);
        }
    }
}

// ---------------------------------------------------------------------------
extern "C" void kernel_launch(void* const* d_in, const int* in_sizes, int n_in,
                              void* d_out, int out_size) {
    const float* x    = (const float*)d_in[0];   // [4096, 4096]
    const float* w    = (const float*)d_in[1];   // [8192, 4096]
    const float* bias = (const float*)d_in[2];   // [8192]
    float* out = (float*)d_out;                  // [4096, 8192]

    cudaFuncSetAttribute(gemm_kernel, cudaFuncAttributeMaxDynamicSharedMemorySize, SMEM_TOTAL);

    convert_all_kernel<<<(NX16 + NW16) / 256, 256>>>(x, w);

    dim3 grid(KN / BN, KM / BM);   // (64, 32)
    gemm_kernel<<<grid, 128, SMEM_TOTAL>>>(bias, out);
}

// round 17
// speedup vs baseline: 1.1801x; 1.0462x over previous
#include <cuda_runtime.h>
#include <cuda_fp16.h>
#include <cstdint>

// ============================================================================
// BanditLayer dense linear: out[4096,8192] = x[4096,4096] @ w[8192,4096]^T + b
//
// Converged design (16 rounds):
//  - fp32->fp16 convert pass (~36us, ~93% of DRAM spec)
//  - mma.sync fp16/fp32-acc GEMM: 128x128 CTA tile, 4 warps (64x64 each),
//    3-stage cp.async pipeline, register double-buffered ldmatrix fragments,
//    2 CTAs/SM, streaming (.cs) epilogue stores.
//  - At the fp32-acc HMMA instruction-rate ceiling (1024 MAC/cyc/SM active).
//  - This round: ks-head reorder — kk=0 fragments issue BEFORE the LDGSTS
//    prefetch burst, so the tensor pipe restarts ~130cyc earlier per k-step.
// ============================================================================

#define KM 4096
#define KP 4096
#define KN 8192

#define BM 128
#define BN 128
#define BK 64
#define STAGES 3
#define KSTEPS (KP / BK)
#define A_STAGE_BYTES (BM * BK * 2)
#define B_STAGE_BYTES (BN * BK * 2)
#define STAGE_BYTES (A_STAGE_BYTES + B_STAGE_BYTES)
#define SMEM_TOTAL (STAGES * STAGE_BYTES)

__device__ __half g_Xh[(size_t)KM * KP];   // 32 MB
__device__ __half g_Wh[(size_t)KN * KP];   // 64 MB

#define NX16 ((KM * KP) / 16)
#define NW16 ((KN * KP) / 16)

// ---------------------------------------------------------------------------
__device__ __forceinline__ uint32_t s2u(const void* p) {
    uint32_t a;
    asm("{ .reg .u64 t; cvta.to.shared.u64 t, %1; cvt.u32.u64 %0, t; }"
        : "=r"(a) : "l"(p));
    return a;
}

__device__ __forceinline__ void cp_async16(uint32_t dst, const void* src) {
    asm volatile("cp.async.cg.shared.global [%0], [%1], 16;" :: "r"(dst), "l"(src));
}
__device__ __forceinline__ void cp_commit() {
    asm volatile("cp.async.commit_group;" ::: "memory");
}
template <int N>
__device__ __forceinline__ void cp_wait() {
    asm volatile("cp.async.wait_group %0;" :: "n"(N) : "memory");
}

__device__ __forceinline__ void ldsm_x4(uint32_t* r, uint32_t addr) {
    asm volatile("ldmatrix.sync.aligned.m8n8.x4.shared.b16 {%0,%1,%2,%3}, [%4];"
                 : "=r"(r[0]), "=r"(r[1]), "=r"(r[2]), "=r"(r[3]) : "r"(addr));
}

// streaming store: evict-first in L2 so output doesn't displace fp16 scratch
__device__ __forceinline__ void stg_cs_v2(float* p, float x, float y) {
    asm volatile("st.global.cs.v2.f32 [%0], {%1, %2};" :: "l"(p), "f"(x), "f"(y) : "memory");
}

#define MMA16816(d, a, b0, b1)                                          \
    asm volatile(                                                       \
        "mma.sync.aligned.m16n8k16.row.col.f32.f16.f16.f32 "            \
        "{%0,%1,%2,%3}, {%4,%5,%6,%7}, {%8,%9}, {%0,%1,%2,%3};"         \
        : "+f"((d)[0]), "+f"((d)[1]), "+f"((d)[2]), "+f"((d)[3])        \
        : "r"((a)[0]), "r"((a)[1]), "r"((a)[2]), "r"((a)[3]),           \
          "r"(b0), "r"(b1))

// swizzled byte offset within a [rows x 64-half] tile (128B rows, 16B chunks)
__device__ __forceinline__ uint32_t swz(int row, int chunk) {
    return (uint32_t)row * 128u + (uint32_t)((chunk ^ (row & 7)) << 4);
}

// ---------------------------------------------------------------------------
// Pass 1: fp32 -> fp16 for BOTH x and weight, 16 elems / thread.
// ---------------------------------------------------------------------------
__global__ void __launch_bounds__(256) convert_all_kernel(const float* __restrict__ x,
                                                          const float* __restrict__ w) {
    int i = blockIdx.x * 256 + threadIdx.x;
    const float* src;
    __half* dst;
    int j;
    if (i < NX16) {
        src = x;  dst = g_Xh;  j = i;
    } else {
        src = w;  dst = g_Wh;  j = i - NX16;
        if (j >= NW16) return;
    }
    const float4* s = reinterpret_cast<const float4*>(src) + (size_t)j * 4;
    uint4* d = reinterpret_cast<uint4*>(dst) + (size_t)j * 2;
    #pragma unroll
    for (int half = 0; half < 2; half++) {
        float4 f0 = s[half * 2 + 0];
        float4 f1 = s[half * 2 + 1];
        alignas(16) __half2 h[4];
        h[0] = __floats2half2_rn(f0.x, f0.y);
        h[1] = __floats2half2_rn(f0.z, f0.w);
        h[2] = __floats2half2_rn(f1.x, f1.y);
        h[3] = __floats2half2_rn(f1.z, f1.w);
        d[half] = *reinterpret_cast<const uint4*>(h);
    }
}

// ---------------------------------------------------------------------------
// Pass 2: the GEMM.
// ---------------------------------------------------------------------------
__global__ void __launch_bounds__(128, 2) gemm_kernel(const float* __restrict__ bias,
                                                      float* __restrict__ out) {
    extern __shared__ char smem[];
    const uint32_t sb = s2u(smem);
    const int tid = threadIdx.x;
    const int lane = tid & 31;
    const int wid = tid >> 5;   // 0..3
    const int nt = blockIdx.x;  // 0..63
    const int mt = blockIdx.y;  // 0..31

    const __half* gA0 = g_Xh + (size_t)(mt * BM) * KP;
    const __half* gW0 = g_Wh + (size_t)(nt * BN) * KP;

    int lrow[8], lcol[8];
    #pragma unroll
    for (int i = 0; i < 8; i++) {
        int idx = i * 128 + tid;
        lrow[i] = idx >> 3;
        lcol[i] = idx & 7;
    }

    auto load_stage = [&](int ks, int buf) {
        uint32_t sA = sb + buf * STAGE_BYTES;
        uint32_t sB = sA + A_STAGE_BYTES;
        const __half* gA = gA0 + ks * BK;
        const __half* gB = gW0 + ks * BK;
        #pragma unroll
        for (int i = 0; i < 8; i++) {
            uint32_t off = swz(lrow[i], lcol[i]);
            cp_async16(sA + off, gA + (size_t)lrow[i] * KP + lcol[i] * 8);
            cp_async16(sB + off, gB + (size_t)lrow[i] * KP + lcol[i] * 8);
        }
    };

    #pragma unroll
    for (int s = 0; s < STAGES - 1; s++) {
        load_stage(s, s);
        cp_commit();
    }

    const int wm = (wid & 1) * 64;
    const int wn = (wid >> 1) * 64;

    float acc[4][8][4];
    #pragma unroll
    for (int mi = 0; mi < 4; mi++)
        #pragma unroll
        for (int ni = 0; ni < 8; ni++)
            #pragma unroll
            for (int q = 0; q < 4; q++) acc[mi][ni][q] = 0.0f;

    const int arow = lane & 15;
    const int achunk = lane >> 4;
    const int brow = (lane & 7) + ((lane >> 4) << 3);
    const int bchunk = (lane >> 3) & 1;

    uint32_t a[2][4][4], b[2][4][4];

    auto load_frags = [&](uint32_t sA, uint32_t sB, int kk, int slot) {
        #pragma unroll
        for (int mi = 0; mi < 4; mi++)
            ldsm_x4(a[slot][mi], sA + swz(wm + mi * 16 + arow, kk * 2 + achunk));
        #pragma unroll
        for (int nj = 0; nj < 4; nj++)
            ldsm_x4(b[slot][nj], sB + swz(wn + nj * 16 + brow, kk * 2 + bchunk));
    };

    for (int ks = 0; ks < KSTEPS; ks++) {
        cp_wait<STAGES - 2>();
        __syncthreads();

        uint32_t sA = sb + (ks % STAGES) * STAGE_BYTES;
        uint32_t sB = sA + A_STAGE_BYTES;

        // ks-head reorder: get kk=0 fragments in flight BEFORE the LDGSTS
        // burst, so the first MMA chain starts as early as possible after
        // the barrier. (frags read buffer ks%3; the prefetch below writes
        // buffer (ks+2)%3 — disjoint.)
        load_frags(sA, sB, 0, 0);

        if (ks + STAGES - 1 < KSTEPS)
            load_stage(ks + STAGES - 1, (ks + STAGES - 1) % STAGES);
        cp_commit();

        #pragma unroll
        for (int kk = 0; kk < BK / 16; kk++) {
            const int cur = kk & 1;
            if (kk + 1 < BK / 16)
                load_frags(sA, sB, kk + 1, cur ^ 1);
            #pragma unroll
            for (int mi = 0; mi < 4; mi++)
                #pragma unroll
                for (int ni = 0; ni < 8; ni++)
                    MMA16816(acc[mi][ni], a[cur][mi],
                             b[cur][ni >> 1][(ni & 1) * 2],
                             b[cur][ni >> 1][(ni & 1) * 2 + 1]);
        }
    }

    // ---- epilogue: streaming gmem stores with bias ----
    const int orow0 = mt * BM + wm + (lane >> 2);
    const int ocol0 = nt * BN + wn + (lane & 3) * 2;

    #pragma unroll
    for (int ni = 0; ni < 8; ni++) {
        int col = ocol0 + ni * 8;
        float2 bv = *reinterpret_cast<const float2*>(bias + col);
        #pragma unroll
        for (int mi = 0; mi < 4; mi++) {
            int r0 = orow0 + mi * 16;
            stg_cs_v2(out + (size_t)r0 * KN + col,
                      acc[mi][ni][0] + bv.x, acc[mi][ni][1] + bv.y);
            stg_cs_v2(out + (size_t)(r0 + 8) * KN + col,
                      acc[mi][ni][2] + bv.x, acc[mi][ni][3] + bv.y);
        }
    }
}

// ---------------------------------------------------------------------------
extern "C" void kernel_launch(void* const* d_in, const int* in_sizes, int n_in,
                              void* d_out, int out_size) {
    const float* x    = (const float*)d_in[0];   // [4096, 4096]
    const float* w    = (const float*)d_in[1];   // [8192, 4096]
    const float* bias = (const float*)d_in[2];   // [8192]
    float* out = (float*)d_out;                  // [4096, 8192]

    cudaFuncSetAttribute(gemm_kernel, cudaFuncAttributeMaxDynamicSharedMemorySize, SMEM_TOTAL);

    convert_all_kernel<<<(NX16 + NW16) / 256, 256>>>(x, w);

    dim3 grid(KN / BN, KM / BM);   // (64, 32)
    gemm_kernel<<<grid, 128, SMEM_TOTAL>>>(bias, out);
}